// round 6
// baseline (speedup 1.0000x reference)
#include <cuda_runtime.h>
#include <cuda_bf16.h>
#include <cuda_fp16.h>
#include <cstdint>
#include <cstddef>

// ============================================================================
// Problem constants
// ============================================================================
#define NROWS  65536
#define DDIM   128
#define KCB    2048
#define DHALF  64

#define TILE_M   128               // z rows per main-kernel block
#define CHUNK_N  128               // emb columns per chunk
#define NCHUNKS  (KCB / CHUNK_N)   // 16
#define NTILES   (NROWS / TILE_M)  // 512
#define CAND_MAX 16

// ============================================================================
// Device scratch (allocation-free rule: __device__ globals)
// ============================================================================
__device__ __half g_Zh[(size_t)NROWS * DHALF];   // fp16 head of z_
__device__ __half g_Eh[KCB * DHALF];             // fp16 head of emb_
__device__ float  g_Zf[(size_t)NROWS * DHALF];   // exact fp32 z_
__device__ float  g_Ef[KCB * DHALF];             // exact fp32 emb_
__device__ float  g_c[KCB];                      // ||emb_k||^2
__device__ float  g_zz[NROWS];                   // ||z_n||^2

// ============================================================================
// PTX helpers (generic sm_80+ PTX only)
// ============================================================================
__device__ __forceinline__ uint32_t smem_u32(const void* p) {
    uint32_t a;
    asm("{ .reg .u64 t; cvta.to.shared.u64 t, %1; cvt.u32.u64 %0, t; }"
        : "=r"(a) : "l"(p));
    return a;
}

__device__ __forceinline__ uint32_t sw128(uint32_t x) { return x ^ ((x >> 3) & 0x70); }

__device__ __forceinline__ void cp_async16(uint32_t dst, const void* src) {
    asm volatile("cp.async.cg.shared.global [%0], [%1], 16;" :: "r"(dst), "l"(src));
}
#define CP_COMMIT()  asm volatile("cp.async.commit_group;" ::: "memory")
#define CP_WAIT(n)   asm volatile("cp.async.wait_group %0;" :: "n"(n) : "memory")

__device__ __forceinline__ void ldsm_x4(uint32_t* r, uint32_t addr) {
    asm volatile("ldmatrix.sync.aligned.m8n8.x4.shared.b16 {%0,%1,%2,%3}, [%4];"
        : "=r"(r[0]), "=r"(r[1]), "=r"(r[2]), "=r"(r[3]) : "r"(addr));
}

__device__ __forceinline__ void mma_f16(float* c, const uint32_t* a,
                                        uint32_t b0, uint32_t b1) {
    asm volatile(
        "mma.sync.aligned.m16n8k16.row.col.f32.f16.f16.f32 "
        "{%0,%1,%2,%3}, {%4,%5,%6,%7}, {%8,%9}, {%0,%1,%2,%3};"
        : "+f"(c[0]), "+f"(c[1]), "+f"(c[2]), "+f"(c[3])
        : "r"(a[0]), "r"(a[1]), "r"(a[2]), "r"(a[3]), "r"(b0), "r"(b1));
}

// ============================================================================
// Prep kernel (merged): blocks [0,32) project emb, blocks [32,1056) project z.
// Emits fp16 head + exact fp32 + row squared-norms (deterministic butterfly).
// ============================================================================
#define PREP_PAD   132
#define PREP_SMEM  ((2 * 64 * PREP_PAD + 64) * 4)

__global__ void __launch_bounds__(256) prep_kernel(const float* __restrict__ z,
                                                   const float* __restrict__ emb,
                                                   const float* __restrict__ W,
                                                   const float* __restrict__ b) {
    extern __shared__ float sm[];
    float* Xs = sm;                        // [64][PREP_PAD]
    float* Ws = sm + 64 * PREP_PAD;        // [64][PREP_PAD]
    float* bs = sm + 2 * 64 * PREP_PAD;    // [64]
    const int tid = threadIdx.x;
    const int bx  = blockIdx.x;
    const int is_emb = (bx < 32);
    const float* X  = is_emb ? emb : z;
    const int row0  = (is_emb ? bx : (bx - 32)) * 64;

    for (int i = tid; i < 64 * 32; i += 256) {
        int r = i >> 5, d4 = i & 31;
        ((float4*)(Xs + r * PREP_PAD))[d4] = ((const float4*)(X + (size_t)(row0 + r) * DDIM))[d4];
        ((float4*)(Ws + r * PREP_PAD))[d4] = ((const float4*)(W + (size_t)r * DDIM))[d4];
    }
    if (tid < 64) bs[tid] = b[tid];
    __syncthreads();

    const int tx = tid & 15, ty = tid >> 4;
    const int r0 = ty * 4;
    float acc[4][4];
#pragma unroll
    for (int i = 0; i < 4; i++)
#pragma unroll
        for (int j = 0; j < 4; j++) acc[i][j] = bs[tx + 16 * j];

    const float4* Xs4 = (const float4*)Xs;   // row stride 33 float4
    const float4* Ws4 = (const float4*)Ws;
#pragma unroll 8
    for (int d4 = 0; d4 < 32; ++d4) {
        float4 a4[4], w4[4];
#pragma unroll
        for (int i = 0; i < 4; i++) a4[i] = Xs4[(r0 + i) * 33 + d4];
#pragma unroll
        for (int j = 0; j < 4; j++) w4[j] = Ws4[(tx + 16 * j) * 33 + d4];
#pragma unroll
        for (int i = 0; i < 4; i++)
#pragma unroll
            for (int j = 0; j < 4; j++) {
                acc[i][j] = fmaf(a4[i].x, w4[j].x, acc[i][j]);
                acc[i][j] = fmaf(a4[i].y, w4[j].y, acc[i][j]);
                acc[i][j] = fmaf(a4[i].z, w4[j].z, acc[i][j]);
                acc[i][j] = fmaf(a4[i].w, w4[j].w, acc[i][j]);
            }
    }

    __half* Oh = is_emb ? g_Eh : g_Zh;
    float*  Of = is_emb ? g_Ef : g_Zf;
    float* cOut = is_emb ? g_c : g_zz;

    float pn[4];
#pragma unroll
    for (int i = 0; i < 4; i++) {
        pn[i] = 0.0f;
#pragma unroll
        for (int j = 0; j < 4; j++) pn[i] = fmaf(acc[i][j], acc[i][j], pn[i]);
    }
#pragma unroll
    for (int off = 1; off < 16; off <<= 1)
#pragma unroll
        for (int i = 0; i < 4; i++)
            pn[i] += __shfl_xor_sync(0xffffffffu, pn[i], off);
    if (tx == 0)
#pragma unroll
        for (int i = 0; i < 4; i++) cOut[row0 + r0 + i] = pn[i];

#pragma unroll
    for (int i = 0; i < 4; i++)
#pragma unroll
        for (int j = 0; j < 4; j++) {
            float v = acc[i][j];
            size_t o = (size_t)(row0 + r0 + i) * DHALF + (tx + 16 * j);
            Oh[o] = __float2half_rn(v);
            Of[o] = v;
        }
}

// ============================================================================
// Main kernel
//
// dynamic smem (bytes):
//   0:      cnt[128] i32        512
//   512:    args[128] i32       512
//   1024:   zz_s[128] f32       512
//   1536:   rowmin[128] f32     512
//   2048:   wmax[8] f32 (+pad)  256  -> 2304
//   2304:   cand[128][16] u16   4096 -> 6400  (pad to 6656)
//   6656:   cs[2048] f32        8192 -> 14848 (pad to 15360, 1KB align)
//   15360:  A tile 16384        -> 31744
//   31744:  B bufs 2 x 16384    -> 64512
//   (refinement overlays zf[128][64] f32 = 32KB at A_OFF)
// ============================================================================
#define CNT_OFF    0u
#define ARGS_OFF   512u
#define ZZS_OFF    1024u
#define RMIN_OFF   1536u
#define WMAX_OFF   2048u
#define CAND_OFF   2304u
#define CS_OFF     6656u
#define A_OFF      15360u
#define B_OFF      31744u
#define MAIN_SMEM  64512

__device__ __forceinline__ void load_B_chunk(uint32_t sb, int chunk, int buf, int tid) {
    const char* src = (const char*)g_Eh + (size_t)chunk * CHUNK_N * 128;  // 128B rows
    uint32_t dstbase = sb + B_OFF + (uint32_t)buf * 16384u;
    for (int i = tid; i < 1024; i += 256) {
        uint32_t off = (uint32_t)(i >> 3) * 128u + (uint32_t)(i & 7) * 16u;
        cp_async16(dstbase + sw128(off), src + off);
    }
}

__global__ void __launch_bounds__(256, 2)
vq_main_kernel(const float* __restrict__ emb,
               float* __restrict__ outQ, float* __restrict__ outOH) {
    extern __shared__ char smem[];
    const uint32_t sb = smem_u32(smem);
    const int tid  = threadIdx.x;
    const int lane = tid & 31;
    const int wid  = tid >> 5;
    const int wm   = wid >> 2;           // 0..1  (row half)
    const int wn   = wid & 3;            // 0..3  (col quarter)
    const int row0 = blockIdx.x * TILE_M;

    int*      cnt_s  = (int*)  (smem + CNT_OFF);
    int*      args   = (int*)  (smem + ARGS_OFF);
    float*    zz_s   = (float*)(smem + ZZS_OFF);
    float*    rmin_s = (float*)(smem + RMIN_OFF);
    float*    wmax_s = (float*)(smem + WMAX_OFF);
    uint16_t* cand_s = (uint16_t*)(smem + CAND_OFF);
    float*    cs     = (float*)(smem + CS_OFF);

    // init + loads
    if (tid < 128) {
        cnt_s[tid]  = 0;
        rmin_s[tid] = __int_as_float(0x7f800000);
        zz_s[tid]   = g_zz[row0 + tid];
    }
    float lmax = 0.0f;
    for (int i = tid; i < KCB; i += 256) {
        float v = g_c[i];
        cs[i] = v;
        lmax = fmaxf(lmax, v);
    }
#pragma unroll
    for (int off = 16; off >= 1; off >>= 1)
        lmax = fmaxf(lmax, __shfl_xor_sync(0xffffffffu, lmax, off));
    if (lane == 0) wmax_s[wid] = lmax;

    // A tile (fp16 head of z~), SW128 swizzled, resident
    {
        const char* src = (const char*)g_Zh + (size_t)row0 * 128;  // 128B rows
        for (int i = tid; i < 1024; i += 256) {
            uint32_t off = (uint32_t)(i >> 3) * 128u + (uint32_t)(i & 7) * 16u;
            cp_async16(sb + A_OFF + sw128(off), src + off);
        }
    }
    load_B_chunk(sb, 0, 0, tid);
    CP_COMMIT();
    CP_WAIT(0);
    __syncthreads();

    float cmax = wmax_s[0];
#pragma unroll
    for (int w = 1; w < 8; ++w) cmax = fmaxf(cmax, wmax_s[w]);

    // ldmatrix lane geometry
    const uint32_t r8     = (uint32_t)((lane & 7) + 8 * ((lane >> 3) & 1));
    const uint32_t xm     = (uint32_t)(lane & 7) * 16u;
    const uint32_t colSel = (uint32_t)((lane >> 4) & 1) * 16u;

    uint32_t aRow[4], bRow[2];
#pragma unroll
    for (int mt = 0; mt < 4; ++mt)
        aRow[mt] = (uint32_t)(wm * 64 + mt * 16) * 128u + r8 * 128u;
#pragma unroll
    for (int ng = 0; ng < 2; ++ng)
        bRow[ng] = (uint32_t)(wn * 32 + ng * 16) * 128u + r8 * 128u;

    // row indices + zz + margin for this lane's 8 row-slots
    int   rowIdx[4][2];
    float zzv[4][2], marg[4][2];
#pragma unroll
    for (int mt = 0; mt < 4; ++mt)
#pragma unroll
        for (int h = 0; h < 2; ++h) {
            int row = wm * 64 + mt * 16 + (lane >> 2) + 8 * h;
            rowIdx[mt][h] = row;
            float zz = zz_s[row];
            zzv[mt][h]  = zz;
            // bound: 2*2^-10.9*||z||*||e||*1.5 + abs slack
            marg[mt][h] = 0.0021f * sqrtf(zz * cmax) + 0.0625f;
        }

    float acc[4][4][4];
#pragma unroll
    for (int mt = 0; mt < 4; ++mt)
#pragma unroll
        for (int nt = 0; nt < 4; ++nt)
#pragma unroll
            for (int q = 0; q < 4; ++q) acc[mt][nt][q] = 0.0f;

    // ---- chunk loop: 16 chunks + 1 rescan of chunk 0 (candidates only) ----
    for (int it = 0; it < 17; ++it) {
        const int cidx = (it < 16) ? it : 0;
        const int buf  = it & 1;
        if (it + 1 < 17) load_B_chunk(sb, (it + 1) & 15, buf ^ 1, tid);
        CP_COMMIT();
        if (it + 1 < 17) CP_WAIT(1); else CP_WAIT(0);
        __syncthreads();

        // thresholds from shared prefix row-min (previous chunks)
        float thr[4][2];
#pragma unroll
        for (int mt = 0; mt < 4; ++mt)
#pragma unroll
            for (int h = 0; h < 2; ++h)
                thr[mt][h] = rmin_s[rowIdx[mt][h]] + marg[mt][h];

        // ---- GEMM: 1 product x 4 k-tiles ----
        const uint32_t aB = sb + A_OFF;
        const uint32_t bB = sb + B_OFF + (uint32_t)buf * 16384u;
#pragma unroll
        for (int kt = 0; kt < 4; ++kt) {
            const uint32_t kc = ((uint32_t)(kt * 32) + colSel) ^ xm;
            uint32_t afr[4][4];
#pragma unroll
            for (int mt = 0; mt < 4; ++mt) ldsm_x4(afr[mt], aB + aRow[mt] + kc);
            uint32_t bfr[2][4];
#pragma unroll
            for (int ng = 0; ng < 2; ++ng) ldsm_x4(bfr[ng], bB + bRow[ng] + kc);
#pragma unroll
            for (int mt = 0; mt < 4; ++mt)
#pragma unroll
                for (int nt = 0; nt < 4; ++nt)
                    mma_f16(acc[mt][nt], afr[mt],
                            bfr[nt >> 1][nt & 1], bfr[nt >> 1][(nt & 1) + 2]);
        }

        // ---- epilogue: distances, candidate accept, row-min update ----
        float bestd[4][2];
#pragma unroll
        for (int mt = 0; mt < 4; ++mt)
#pragma unroll
            for (int h = 0; h < 2; ++h) bestd[mt][h] = __int_as_float(0x7f800000);

        const int colbase = cidx * CHUNK_N + wn * 32 + 2 * (lane & 3);
#pragma unroll
        for (int mt = 0; mt < 4; ++mt)
#pragma unroll
            for (int nt = 0; nt < 4; ++nt) {
                const int c0 = colbase + nt * 8;
                const float cv0 = cs[c0], cv1 = cs[c0 + 1];
#pragma unroll
                for (int h = 0; h < 2; ++h) {
                    float d0 = fmaf(-2.0f, acc[mt][nt][2 * h + 0], zzv[mt][h] + cv0);
                    float d1 = fmaf(-2.0f, acc[mt][nt][2 * h + 1], zzv[mt][h] + cv1);
                    if (it >= 1) {
                        if (d0 < thr[mt][h]) {
                            int slot = atomicAdd(&cnt_s[rowIdx[mt][h]], 1);
                            if (slot < CAND_MAX)
                                cand_s[rowIdx[mt][h] * CAND_MAX + slot] = (uint16_t)c0;
                        }
                        if (d1 < thr[mt][h]) {
                            int slot = atomicAdd(&cnt_s[rowIdx[mt][h]], 1);
                            if (slot < CAND_MAX)
                                cand_s[rowIdx[mt][h] * CAND_MAX + slot] = (uint16_t)(c0 + 1);
                        }
                    }
                    bestd[mt][h] = fminf(bestd[mt][h], fminf(d0, d1));
                    acc[mt][nt][2 * h + 0] = 0.0f;
                    acc[mt][nt][2 * h + 1] = 0.0f;
                }
            }

        // quad tighten + benign-race shared row-min update (never raises)
#pragma unroll
        for (int mt = 0; mt < 4; ++mt)
#pragma unroll
            for (int h = 0; h < 2; ++h) {
                float bq = bestd[mt][h];
                bq = fminf(bq, __shfl_xor_sync(0xffffffffu, bq, 1));
                bq = fminf(bq, __shfl_xor_sync(0xffffffffu, bq, 2));
                if ((lane & 3) == 0 && bq < rmin_s[rowIdx[mt][h]])
                    rmin_s[rowIdx[mt][h]] = bq;
            }

        // ---- overlapped one-hot zero-fill for this chunk's 128-col slice ----
        if (it < 16) {
            const float4 z4 = make_float4(0.f, 0.f, 0.f, 0.f);
            float4* base = (float4*)(outOH) + (size_t)row0 * (KCB / 4) + cidx * 32;
            for (int i = tid; i < 128 * 32; i += 256) {
                int r = i >> 5, c4 = i & 31;
                __stcs(base + (size_t)r * (KCB / 4) + c4, z4);
            }
        }

        __syncthreads();   // rowmin visible + buf free before next prefetch use
    }

    // ---- refinement: exact fp32 over candidates (warp per 16 rows) ----
    float* zf = (float*)(smem + A_OFF);   // overlay, GEMM done
    for (int i = tid; i < 128 * 16; i += 256)
        ((float4*)zf)[i] = ((const float4*)(g_Zf + (size_t)row0 * DHALF))[i];
    __syncthreads();

    {
        const float2* zf2base = (const float2*)zf;
        for (int rr = 0; rr < 16; ++rr) {
            const int row = wid * 16 + rr;
            const int n = cnt_s[row];
            const float zz = zz_s[row];
            const float2 zv = zf2base[row * 32 + lane];
            float bd = __int_as_float(0x7f800000);
            int   bi = KCB;
            if (n <= CAND_MAX) {
                for (int c = 0; c < n; ++c) {
                    int k = cand_s[row * CAND_MAX + c];
                    float2 ev = __ldg((const float2*)(g_Ef + (size_t)k * DHALF) + lane);
                    float p = fmaf(zv.x, ev.x, zv.y * ev.y);
#pragma unroll
                    for (int off = 16; off >= 1; off >>= 1)
                        p += __shfl_xor_sync(0xffffffffu, p, off);
                    float d = zz + cs[k] - 2.0f * p;
                    if (d < bd || (d == bd && k < bi)) { bd = d; bi = k; }
                }
            } else {
                // rare overflow: full fp32 scan, lane-strided
                for (int k = lane; k < KCB; k += 32) {
                    const float* e = g_Ef + (size_t)k * DHALF;
                    float s = 0.0f;
                    const float* zrow = zf + row * DHALF;
#pragma unroll 16
                    for (int d = 0; d < DHALF; ++d) s = fmaf(zrow[d], __ldg(e + d), s);
                    float dd = zz + cs[k] - 2.0f * s;
                    if (dd < bd || (dd == bd && k < bi)) { bd = dd; bi = k; }
                }
#pragma unroll
                for (int off = 16; off >= 1; off >>= 1) {
                    float od = __shfl_xor_sync(0xffffffffu, bd, off);
                    int   oi = __shfl_xor_sync(0xffffffffu, bi, off);
                    if (od < bd || (od == bd && oi < bi)) { bd = od; bi = oi; }
                }
            }
            if (lane == 0) args[row] = bi;
        }
    }
    __syncthreads();

    // ---- one-hot scatter (zeros already streamed during the loop) ----
    if (tid < 128)
        outOH[(size_t)(row0 + tid) * KCB + args[tid]] = 1.0f;

    // ---- quantized gather: 128 rows x 32 float4 from original embeddings ----
    {
        const float4* e4 = (const float4*)emb;
        for (int i = tid; i < 128 * 32; i += 256) {
            int r = i >> 5, c = i & 31;
            float4 v = __ldg(e4 + (size_t)args[r] * 32 + c);
            __stcs((float4*)outQ + (size_t)(row0 + r) * 32 + c, v);
        }
    }
}

// ============================================================================
// Launch
// ============================================================================
extern "C" void kernel_launch(void* const* d_in, const int* in_sizes, int n_in,
                              void* d_out, int out_size) {
    const float* z   = (const float*)d_in[0];
    const float* W   = (const float*)d_in[1];
    const float* b   = (const float*)d_in[2];
    const float* emb = (const float*)d_in[3];

    float* outQ  = (float*)d_out;                 // [N, 128]
    float* outOH = outQ + (size_t)NROWS * DDIM;   // [N, 2048]

    cudaFuncSetAttribute(prep_kernel, cudaFuncAttributeMaxDynamicSharedMemorySize, PREP_SMEM);
    cudaFuncSetAttribute(vq_main_kernel, cudaFuncAttributeMaxDynamicSharedMemorySize, MAIN_SMEM);

    prep_kernel<<<32 + NROWS / 64, 256, PREP_SMEM>>>(z, emb, W, b);
    vq_main_kernel<<<NTILES, 256, MAIN_SMEM>>>(emb, outQ, outOH);
}

// round 7
// speedup vs baseline: 5.8617x; 5.8617x over previous
#include <cuda_runtime.h>
#include <cuda_bf16.h>
#include <cuda_fp16.h>
#include <cstdint>
#include <cstddef>

// ============================================================================
// Problem constants
// ============================================================================
#define NROWS  65536
#define DDIM   128
#define KCB    2048
#define DHALF  64

#define TILE_M   128
#define CHUNK_N  128
#define NCHUNKS  (KCB / CHUNK_N)   // 16
#define NTILES   (NROWS / TILE_M)  // 512

// ============================================================================
// Device scratch
// ============================================================================
__device__ __half g_Zh[(size_t)NROWS * DHALF];   // fp16 head of z_
__device__ __half g_Eh[KCB * DHALF];             // fp16 head of emb_
__device__ float  g_Zf[(size_t)NROWS * DHALF];   // exact fp32 z_
__device__ float  g_Ef[KCB * DHALF];             // exact fp32 emb_
__device__ float  g_c[KCB];                      // ||emb_k||^2
__device__ float  g_zz[NROWS];                   // ||z_n||^2

// ============================================================================
// PTX helpers (generic sm_80+ PTX only)
// ============================================================================
__device__ __forceinline__ uint32_t smem_u32(const void* p) {
    uint32_t a;
    asm("{ .reg .u64 t; cvta.to.shared.u64 t, %1; cvt.u32.u64 %0, t; }"
        : "=r"(a) : "l"(p));
    return a;
}

__device__ __forceinline__ uint32_t sw128(uint32_t x) { return x ^ ((x >> 3) & 0x70); }

__device__ __forceinline__ void cp_async16(uint32_t dst, const void* src) {
    asm volatile("cp.async.cg.shared.global [%0], [%1], 16;" :: "r"(dst), "l"(src));
}
#define CP_COMMIT()  asm volatile("cp.async.commit_group;" ::: "memory")
#define CP_WAIT(n)   asm volatile("cp.async.wait_group %0;" :: "n"(n) : "memory")

__device__ __forceinline__ void ldsm_x4(uint32_t* r, uint32_t addr) {
    asm volatile("ldmatrix.sync.aligned.m8n8.x4.shared.b16 {%0,%1,%2,%3}, [%4];"
        : "=r"(r[0]), "=r"(r[1]), "=r"(r[2]), "=r"(r[3]) : "r"(addr));
}

__device__ __forceinline__ void mma_f16(float* c, const uint32_t* a,
                                        uint32_t b0, uint32_t b1) {
    asm volatile(
        "mma.sync.aligned.m16n8k16.row.col.f32.f16.f16.f32 "
        "{%0,%1,%2,%3}, {%4,%5,%6,%7}, {%8,%9}, {%0,%1,%2,%3};"
        : "+f"(c[0]), "+f"(c[1]), "+f"(c[2]), "+f"(c[3])
        : "r"(a[0]), "r"(a[1]), "r"(a[2]), "r"(a[3]), "r"(b0), "r"(b1));
}

// ============================================================================
// Prep kernel (merged): blocks [0,32) project emb, blocks [32,1056) project z.
// ============================================================================
#define PREP_PAD   132
#define PREP_SMEM  ((2 * 64 * PREP_PAD + 64) * 4)

__global__ void __launch_bounds__(256) prep_kernel(const float* __restrict__ z,
                                                   const float* __restrict__ emb,
                                                   const float* __restrict__ W,
                                                   const float* __restrict__ b) {
    extern __shared__ float sm[];
    float* Xs = sm;
    float* Ws = sm + 64 * PREP_PAD;
    float* bs = sm + 2 * 64 * PREP_PAD;
    const int tid = threadIdx.x;
    const int bx  = blockIdx.x;
    const int is_emb = (bx < 32);
    const float* X  = is_emb ? emb : z;
    const int row0  = (is_emb ? bx : (bx - 32)) * 64;

    for (int i = tid; i < 64 * 32; i += 256) {
        int r = i >> 5, d4 = i & 31;
        ((float4*)(Xs + r * PREP_PAD))[d4] = ((const float4*)(X + (size_t)(row0 + r) * DDIM))[d4];
        ((float4*)(Ws + r * PREP_PAD))[d4] = ((const float4*)(W + (size_t)r * DDIM))[d4];
    }
    if (tid < 64) bs[tid] = b[tid];
    __syncthreads();

    const int tx = tid & 15, ty = tid >> 4;
    const int r0 = ty * 4;
    float acc[4][4];
#pragma unroll
    for (int i = 0; i < 4; i++)
#pragma unroll
        for (int j = 0; j < 4; j++) acc[i][j] = bs[tx + 16 * j];

    const float4* Xs4 = (const float4*)Xs;
    const float4* Ws4 = (const float4*)Ws;
#pragma unroll 8
    for (int d4 = 0; d4 < 32; ++d4) {
        float4 a4[4], w4[4];
#pragma unroll
        for (int i = 0; i < 4; i++) a4[i] = Xs4[(r0 + i) * 33 + d4];
#pragma unroll
        for (int j = 0; j < 4; j++) w4[j] = Ws4[(tx + 16 * j) * 33 + d4];
#pragma unroll
        for (int i = 0; i < 4; i++)
#pragma unroll
            for (int j = 0; j < 4; j++) {
                acc[i][j] = fmaf(a4[i].x, w4[j].x, acc[i][j]);
                acc[i][j] = fmaf(a4[i].y, w4[j].y, acc[i][j]);
                acc[i][j] = fmaf(a4[i].z, w4[j].z, acc[i][j]);
                acc[i][j] = fmaf(a4[i].w, w4[j].w, acc[i][j]);
            }
    }

    __half* Oh = is_emb ? g_Eh : g_Zh;
    float*  Of = is_emb ? g_Ef : g_Zf;
    float* cOut = is_emb ? g_c : g_zz;

    float pn[4];
#pragma unroll
    for (int i = 0; i < 4; i++) {
        pn[i] = 0.0f;
#pragma unroll
        for (int j = 0; j < 4; j++) pn[i] = fmaf(acc[i][j], acc[i][j], pn[i]);
    }
#pragma unroll
    for (int off = 1; off < 16; off <<= 1)
#pragma unroll
        for (int i = 0; i < 4; i++)
            pn[i] += __shfl_xor_sync(0xffffffffu, pn[i], off);
    if (tx == 0)
#pragma unroll
        for (int i = 0; i < 4; i++) cOut[row0 + r0 + i] = pn[i];

#pragma unroll
    for (int i = 0; i < 4; i++)
#pragma unroll
        for (int j = 0; j < 4; j++) {
            float v = acc[i][j];
            size_t o = (size_t)(row0 + r0 + i) * DHALF + (tx + 16 * j);
            Oh[o] = __float2half_rn(v);
            Of[o] = v;
        }
}

// ============================================================================
// Main kernel — smem layout (bytes):
//   0:      args[128] i32      512
//   512:    zz_s[128] f32      512
//   1024:   wmax[8] f32        (pad to 1280)
//   1280:   red_d [128][4]     2048 -> 3328
//   3328:   red_i [128][4]     2048 -> 5376
//   5376:   red_d2[128][4]     2048 -> 7424
//   7424:   chunkmin[128][16]  8192 -> 15616
//   15616:  cs[2048] f32       8192 -> 23808 (pad to 24576)
//   24576:  A tile 16384       -> 40960
//   40960:  B bufs 2 x 16384   -> 73728
//   (refinement overlays zf[128][64] f32 = 32KB at A_OFF, after GEMM)
// ============================================================================
#define ARGS_OFF   0u
#define ZZS_OFF    512u
#define WMAX_OFF   1024u
#define RED_D_OFF  1280u
#define RED_I_OFF  3328u
#define RED_D2_OFF 5376u
#define CMIN_OFF   7424u
#define CS_OFF     15616u
#define A_OFF      24576u
#define B_OFF      40960u
#define MAIN_SMEM  73728

__device__ __forceinline__ void load_B_chunk(uint32_t sb, int chunk, int buf, int tid) {
    const char* src = (const char*)g_Eh + (size_t)chunk * CHUNK_N * 128;
    uint32_t dstbase = sb + B_OFF + (uint32_t)buf * 16384u;
    for (int i = tid; i < 1024; i += 256) {
        uint32_t off = (uint32_t)(i >> 3) * 128u + (uint32_t)(i & 7) * 16u;
        cp_async16(dstbase + sw128(off), src + off);
    }
}

__global__ void __launch_bounds__(256, 2)
vq_main_kernel(const float* __restrict__ emb,
               float* __restrict__ outQ, float* __restrict__ outOH) {
    extern __shared__ char smem[];
    const uint32_t sb = smem_u32(smem);
    const int tid  = threadIdx.x;
    const int lane = tid & 31;
    const int wid  = tid >> 5;
    const int wm   = wid >> 2;
    const int wn   = wid & 3;
    const int row0 = blockIdx.x * TILE_M;

    int*   args   = (int*)  (smem + ARGS_OFF);
    float* zz_s   = (float*)(smem + ZZS_OFF);
    float* wmax_s = (float*)(smem + WMAX_OFF);
    float* red_d  = (float*)(smem + RED_D_OFF);
    int*   red_i  = (int*)  (smem + RED_I_OFF);
    float* red_d2 = (float*)(smem + RED_D2_OFF);
    int*   cmin_s = (int*)  (smem + CMIN_OFF);
    float* cs     = (float*)(smem + CS_OFF);

    if (tid < 128) zz_s[tid] = g_zz[row0 + tid];
    for (int i = tid; i < 128 * 16; i += 256) cmin_s[i] = 0x7f800000;  // +inf bits

    float lmax = 0.0f;
    for (int i = tid; i < KCB; i += 256) {
        float v = g_c[i];
        cs[i] = v;
        lmax = fmaxf(lmax, v);
    }
#pragma unroll
    for (int off = 16; off >= 1; off >>= 1)
        lmax = fmaxf(lmax, __shfl_xor_sync(0xffffffffu, lmax, off));
    if (lane == 0) wmax_s[wid] = lmax;

    // A tile (fp16 head of z~), SW128 swizzled, resident
    {
        const char* src = (const char*)g_Zh + (size_t)row0 * 128;
        for (int i = tid; i < 1024; i += 256) {
            uint32_t off = (uint32_t)(i >> 3) * 128u + (uint32_t)(i & 7) * 16u;
            cp_async16(sb + A_OFF + sw128(off), src + off);
        }
    }
    load_B_chunk(sb, 0, 0, tid);
    CP_COMMIT();
    CP_WAIT(0);
    __syncthreads();

    float cmax = wmax_s[0];
#pragma unroll
    for (int w = 1; w < 8; ++w) cmax = fmaxf(cmax, wmax_s[w]);

    // ldmatrix lane geometry
    const uint32_t r8     = (uint32_t)((lane & 7) + 8 * ((lane >> 3) & 1));
    const uint32_t xm     = (uint32_t)(lane & 7) * 16u;
    const uint32_t colSel = (uint32_t)((lane >> 4) & 1) * 16u;

    uint32_t aRow[4], bRow[2];
#pragma unroll
    for (int mt = 0; mt < 4; ++mt)
        aRow[mt] = (uint32_t)(wm * 64 + mt * 16) * 128u + r8 * 128u;
#pragma unroll
    for (int ng = 0; ng < 2; ++ng)
        bRow[ng] = (uint32_t)(wn * 32 + ng * 16) * 128u + r8 * 128u;

    int   rowIdx[4][2];
    float zzv[4][2];
#pragma unroll
    for (int mt = 0; mt < 4; ++mt)
#pragma unroll
        for (int h = 0; h < 2; ++h) {
            int row = wm * 64 + mt * 16 + (lane >> 2) + 8 * h;
            rowIdx[mt][h] = row;
            zzv[mt][h]  = zz_s[row];
        }

    float acc[4][4][4];
#pragma unroll
    for (int mt = 0; mt < 4; ++mt)
#pragma unroll
        for (int nt = 0; nt < 4; ++nt)
#pragma unroll
            for (int q = 0; q < 4; ++q) acc[mt][nt][q] = 0.0f;

    // persistent per-lane running state: best, best-index, second-best
    float b1[4][2], b2[4][2];
    int   i1[4][2];
#pragma unroll
    for (int mt = 0; mt < 4; ++mt)
#pragma unroll
        for (int h = 0; h < 2; ++h) {
            b1[mt][h] = __int_as_float(0x7f800000);
            b2[mt][h] = __int_as_float(0x7f800000);
            i1[mt][h] = 0;
        }

    // ---- chunk loop ----
    for (int chunk = 0; chunk < NCHUNKS; ++chunk) {
        const int buf = chunk & 1;
        if (chunk + 1 < NCHUNKS) load_B_chunk(sb, chunk + 1, buf ^ 1, tid);
        CP_COMMIT();
        if (chunk + 1 < NCHUNKS) CP_WAIT(1); else CP_WAIT(0);
        __syncthreads();

        // ---- GEMM: hh product, 4 k-tiles ----
        const uint32_t aB = sb + A_OFF;
        const uint32_t bB = sb + B_OFF + (uint32_t)buf * 16384u;
#pragma unroll
        for (int kt = 0; kt < 4; ++kt) {
            const uint32_t kc = ((uint32_t)(kt * 32) + colSel) ^ xm;
            uint32_t afr[4][4];
#pragma unroll
            for (int mt = 0; mt < 4; ++mt) ldsm_x4(afr[mt], aB + aRow[mt] + kc);
            uint32_t bfr[2][4];
#pragma unroll
            for (int ng = 0; ng < 2; ++ng) ldsm_x4(bfr[ng], bB + bRow[ng] + kc);
#pragma unroll
            for (int mt = 0; mt < 4; ++mt)
#pragma unroll
                for (int nt = 0; nt < 4; ++nt)
                    mma_f16(acc[mt][nt], afr[mt],
                            bfr[nt >> 1][nt & 1], bfr[nt >> 1][(nt & 1) + 2]);
        }

        // ---- epilogue: distances, running best/second, chunk minima ----
        const int colbase = chunk * CHUNK_N + wn * 32 + 2 * (lane & 3);
#pragma unroll
        for (int mt = 0; mt < 4; ++mt)
#pragma unroll
            for (int h = 0; h < 2; ++h) {
                float cmin = __int_as_float(0x7f800000);
#pragma unroll
                for (int nt = 0; nt < 4; ++nt) {
                    const int c0 = colbase + nt * 8;
                    float d0 = fmaf(-2.0f, acc[mt][nt][2 * h + 0], zzv[mt][h] + cs[c0]);
                    float d1 = fmaf(-2.0f, acc[mt][nt][2 * h + 1], zzv[mt][h] + cs[c0 + 1]);
                    // ascending column order => strict < keeps first index
                    if (d0 < b1[mt][h]) { b2[mt][h] = b1[mt][h]; b1[mt][h] = d0; i1[mt][h] = c0; }
                    else                 b2[mt][h] = fminf(b2[mt][h], d0);
                    if (d1 < b1[mt][h]) { b2[mt][h] = b1[mt][h]; b1[mt][h] = d1; i1[mt][h] = c0 + 1; }
                    else                 b2[mt][h] = fminf(b2[mt][h], d1);
                    cmin = fminf(cmin, fminf(d0, d1));
                    acc[mt][nt][2 * h + 0] = 0.0f;
                    acc[mt][nt][2 * h + 1] = 0.0f;
                }
                // quad min then one atomicMin per row-slot (positive floats)
                cmin = fminf(cmin, __shfl_xor_sync(0xffffffffu, cmin, 1));
                cmin = fminf(cmin, __shfl_xor_sync(0xffffffffu, cmin, 2));
                if ((lane & 3) == 0)
                    atomicMin(&cmin_s[rowIdx[mt][h] * 16 + chunk], __float_as_int(cmin));
            }

        // ---- overlapped one-hot zero-fill for this chunk's 128-col slice ----
        {
            const float4 z4 = make_float4(0.f, 0.f, 0.f, 0.f);
            float4* base = (float4*)(outOH) + (size_t)row0 * (KCB / 4) + chunk * 32;
            for (int i = tid; i < 128 * 32; i += 256) {
                int r = i >> 5, c4 = i & 31;
                __stcs(base + (size_t)r * (KCB / 4) + c4, z4);
            }
        }

        __syncthreads();
    }

    // ---- quad merge of (b1,i1,b2), then cross-warp ----
#pragma unroll
    for (int mt = 0; mt < 4; ++mt)
#pragma unroll
        for (int h = 0; h < 2; ++h) {
            float vb1 = b1[mt][h], vb2 = b2[mt][h];
            int   vi1 = i1[mt][h];
#pragma unroll
            for (int off = 1; off < 4; off <<= 1) {
                float ob1 = __shfl_xor_sync(0xffffffffu, vb1, off);
                int   oi1 = __shfl_xor_sync(0xffffffffu, vi1, off);
                float ob2 = __shfl_xor_sync(0xffffffffu, vb2, off);
                bool take = (ob1 < vb1) || (ob1 == vb1 && oi1 < vi1);
                float nb2 = take ? fminf(vb1, ob2) : fminf(vb2, ob1);
                if (take) { vb1 = ob1; vi1 = oi1; }
                vb2 = nb2;
            }
            if ((lane & 3) == 0) {
                int row = rowIdx[mt][h];
                red_d [row * 4 + wn] = vb1;
                red_i [row * 4 + wn] = vi1;
                red_d2[row * 4 + wn] = vb2;
            }
        }
    __syncthreads();

    if (tid < 128) {
        float vb1 = red_d[tid * 4], vb2 = red_d2[tid * 4];
        int   vi1 = red_i[tid * 4];
#pragma unroll
        for (int w = 1; w < 4; ++w) {
            float ob1 = red_d[tid * 4 + w];
            int   oi1 = red_i[tid * 4 + w];
            float ob2 = red_d2[tid * 4 + w];
            bool take = (ob1 < vb1) || (ob1 == vb1 && oi1 < vi1);
            float nb2 = take ? fminf(vb1, ob2) : fminf(vb2, ob1);
            if (take) { vb1 = ob1; vi1 = oi1; }
            vb2 = nb2;
        }
        args[tid] = vi1;
        red_d [tid * 4] = vb1;   // final best
        red_d2[tid * 4] = vb2;   // final second-best
    }
    __syncthreads();

    // ---- load exact z_ tile into smem overlay (GEMM buffers dead now) ----
    float* zf = (float*)(smem + A_OFF);
    for (int i = tid; i < 128 * 16; i += 256)
        ((float4*)zf)[i] = ((const float4*)(g_Zf + (size_t)row0 * DHALF))[i];
    __syncthreads();

    // ---- refinement: only ambiguous rows; only surviving chunks; exact fp32 ----
    for (int rr = 0; rr < 16; ++rr) {
        const int row = wid * 16 + rr;
        const float fb1 = red_d[row * 4];
        const float fb2 = red_d2[row * 4];
        const float zz  = zz_s[row];
        // deterministic hh error bound: 2 * 2^-10 * ||z|| * ||e||, safety 2.7x
        const float M = 0.0052f * sqrtf(zz * cmax) + 0.01f;
        if (fb2 - fb1 >= M) continue;          // hh argmin provably exact

        const float thr = fb1 + M;
        const float4* zrow4 = (const float4*)(zf + row * DHALF);
        float bd = __int_as_float(0x7f800000);
        int   bi = KCB;
        for (int ch = 0; ch < NCHUNKS; ++ch) {
            if (__int_as_float(cmin_s[row * 16 + ch]) > thr) continue;
            // lane refines 4 consecutive codes exactly
            const int k0 = ch * CHUNK_N + lane * 4;
#pragma unroll
            for (int j = 0; j < 4; ++j) {
                const int k = k0 + j;
                const float4* e4 = (const float4*)(g_Ef + (size_t)k * DHALF);
                float s = 0.0f;
#pragma unroll
                for (int d4 = 0; d4 < 16; ++d4) {
                    float4 zv = zrow4[d4];
                    float4 ev = __ldg(e4 + d4);
                    s = fmaf(zv.x, ev.x, s);
                    s = fmaf(zv.y, ev.y, s);
                    s = fmaf(zv.z, ev.z, s);
                    s = fmaf(zv.w, ev.w, s);
                }
                float d = zz + cs[k] - 2.0f * s;
                if (d < bd || (d == bd && k < bi)) { bd = d; bi = k; }
            }
        }
        // warp argmin (lanes ascending k => first-index preserved by tie rule)
#pragma unroll
        for (int off = 16; off >= 1; off >>= 1) {
            float od = __shfl_xor_sync(0xffffffffu, bd, off);
            int   oi = __shfl_xor_sync(0xffffffffu, bi, off);
            if (od < bd || (od == bd && oi < bi)) { bd = od; bi = oi; }
        }
        if (lane == 0) args[row] = bi;
    }
    __syncthreads();

    // ---- one-hot scatter (zeros already streamed during the loop) ----
    if (tid < 128)
        outOH[(size_t)(row0 + tid) * KCB + args[tid]] = 1.0f;

    // ---- quantized gather ----
    {
        const float4* e4 = (const float4*)emb;
        for (int i = tid; i < 128 * 32; i += 256) {
            int r = i >> 5, c = i & 31;
            float4 v = __ldg(e4 + (size_t)args[r] * 32 + c);
            __stcs((float4*)outQ + (size_t)(row0 + r) * 32 + c, v);
        }
    }
}

// ============================================================================
// Launch
// ============================================================================
extern "C" void kernel_launch(void* const* d_in, const int* in_sizes, int n_in,
                              void* d_out, int out_size) {
    const float* z   = (const float*)d_in[0];
    const float* W   = (const float*)d_in[1];
    const float* b   = (const float*)d_in[2];
    const float* emb = (const float*)d_in[3];

    float* outQ  = (float*)d_out;                 // [N, 128]
    float* outOH = outQ + (size_t)NROWS * DDIM;   // [N, 2048]

    cudaFuncSetAttribute(prep_kernel, cudaFuncAttributeMaxDynamicSharedMemorySize, PREP_SMEM);
    cudaFuncSetAttribute(vq_main_kernel, cudaFuncAttributeMaxDynamicSharedMemorySize, MAIN_SMEM);

    prep_kernel<<<32 + NROWS / 64, 256, PREP_SMEM>>>(z, emb, W, b);
    vq_main_kernel<<<NTILES, 256, MAIN_SMEM>>>(emb, outQ, outOH);
}